// round 2
// baseline (speedup 1.0000x reference)
#include <cuda_runtime.h>
#include <math.h>

#define B_ROWS 8192
#define MCOLS  8199
#define MPAD   8320      // 65 * 128
#define H      128
#define EDIM   256
#define NCLS   7
#define NRT    64        // row tiles of 128
#define NCT    65        // col tiles of 128
#define TEMPC  0.07

__device__ float g_rn[MPAD * H];            // normalized rows (4.26 MB, L2 resident)
__device__ int   g_lab[MPAD];
__device__ int   g_ccount[NCLS];
__device__ float g_allp[NCT * B_ROWS];      // per-coltile partial: sum of e (diag & pad removed)
__device__ float g_matchp[NCT * B_ROWS];    // per-coltile partial: sum of e over label matches
__device__ float g_lv[B_ROWS];
__device__ float g_lm[B_ROWS];

// fast exp2 for t in [0, ~21]: round-to-nearest int via magic, deg-5 poly on [-0.5,0.5]
__device__ __forceinline__ float exp2fast(float t) {
    float kf = t + 12582912.0f;              // 1.5 * 2^23
    int   ki = __float_as_int(kf);
    float n  = kf - 12582912.0f;
    float r  = t - n;
    float p  = 0.0013333558f;
    p = fmaf(p, r, 0.0096181291f);
    p = fmaf(p, r, 0.0555041087f);
    p = fmaf(p, r, 0.2402265069f);
    p = fmaf(p, r, 0.6931471806f);
    p = fmaf(p, r, 1.0f);
    return p * __int_as_float((ki << 23) + 0x3f800000);
}

// ---------------- kernel Z: zero class-count histogram ----------------
__global__ void k_zero() {
    if (threadIdx.x < NCLS) g_ccount[threadIdx.x] = 0;
}

// ---------------- kernel A: fc(centers), normalize all rows, labels, histogram ----------------
__global__ void k_prep(const float* __restrict__ reps, const int* __restrict__ labels,
                       const float* __restrict__ centers, const float* __restrict__ fc_w,
                       const float* __restrict__ fc_b) {
    int bid = blockIdx.x;
    int t   = threadIdx.x;   // 0..127
    float x = 0.0f;
    int lab = -1;
    if (bid < B_ROWS) {
        x = reps[bid * H + t];
        lab = labels[bid];
    } else if (bid < MCOLS) {
        int c = bid - B_ROWS;
        float acc = fc_b[t];
        const float* cw = centers + c * EDIM;
        const float* w  = fc_w + t * EDIM;
        #pragma unroll 8
        for (int e = 0; e < EDIM; e++) acc = fmaf(cw[e], w[e], acc);
        x = acc;
        lab = c;
    }
    // block reduce sum of squares (128 threads)
    float s = x * x;
    #pragma unroll
    for (int o = 16; o; o >>= 1) s += __shfl_xor_sync(0xffffffffu, s, o);
    __shared__ float ws[4];
    int w = t >> 5, l = t & 31;
    if (l == 0) ws[w] = s;
    __syncthreads();
    float tot = ws[0] + ws[1] + ws[2] + ws[3];
    float inv = 1.0f / fmaxf(sqrtf(tot), 1e-8f);
    g_rn[bid * H + t] = x * inv;     // pad rows: x==0 -> writes 0
    if (t == 0) {
        g_lab[bid] = lab;
        if (bid < MCOLS) atomicAdd(&g_ccount[lab], 1);
    }
}

// ---------------- kernel B: fused cos-GEMM + exp + masked row sums ----------------
__global__ __launch_bounds__(256, 2) void k_main() {
    const int rt = blockIdx.x;       // row tile  (64)
    const int ct = blockIdx.y;       // col tile  (65)
    const int tid = threadIdx.x;
    const int tx = tid & 15;         // 0..15 -> 8 cols each
    const int ty = tid >> 4;         // 0..15 -> 8 rows each
    const int i0 = rt * 128;
    const int j0 = ct * 128;

    __shared__ float sA[32 * 128];   // k-major, XOR-swizzled groups
    __shared__ float sB[32 * 128];
    __shared__ int   sLI[128];
    __shared__ int   sLJ[128];

    if (tid < 128) sLI[tid] = g_lab[i0 + tid];
    else           sLJ[tid - 128] = g_lab[j0 + tid - 128];

    unsigned long long acc2[32];     // 4 row-pairs x 8 cols, packed f32x2
    #pragma unroll
    for (int q = 0; q < 32; q++) acc2[q] = 0ull;

    const float* Abase = g_rn + (size_t)i0 * H;
    const float* Bbase = g_rn + (size_t)j0 * H;
    const int lq = tid & 7;          // which k-quad within 32-k chunk
    const int lr = tid >> 3;         // 0..31 row within pass

    for (int kc = 0; kc < H; kc += 32) {
        float4 va[4], vb[4];
        #pragma unroll
        for (int p = 0; p < 4; p++) {
            int r = lr + p * 32;
            va[p] = *(const float4*)(Abase + r * H + kc + lq * 4);
            vb[p] = *(const float4*)(Bbase + r * H + kc + lq * 4);
        }
        __syncthreads();             // previous chunk's compute done
        #pragma unroll
        for (int p = 0; p < 4; p++) {
            int r = lr + p * 32;
            int off = ((((r >> 2) ^ lq) << 2) | (r & 3));   // fk for kk=4lq+c is lq
            sA[(lq * 4 + 0) * 128 + off] = va[p].x;
            sA[(lq * 4 + 1) * 128 + off] = va[p].y;
            sA[(lq * 4 + 2) * 128 + off] = va[p].z;
            sA[(lq * 4 + 3) * 128 + off] = va[p].w;
            sB[(lq * 4 + 0) * 128 + off] = vb[p].x;
            sB[(lq * 4 + 1) * 128 + off] = vb[p].y;
            sB[(lq * 4 + 2) * 128 + off] = vb[p].z;
            sB[(lq * 4 + 3) * 128 + off] = vb[p].w;
        }
        __syncthreads();

        #pragma unroll 8
        for (int k = 0; k < 32; k++) {
            const int fk = (k >> 2) & 7;
            const float* Ak = sA + k * 128;
            const float* Bk = sB + k * 128;
            ulonglong2 a0 = *(const ulonglong2*)(Ak + (((2 * ty + 0) ^ fk) << 2));
            ulonglong2 a1 = *(const ulonglong2*)(Ak + (((2 * ty + 1) ^ fk) << 2));
            float4 b0 = *(const float4*)(Bk + (((2 * tx + 0) ^ fk) << 2));
            float4 b1 = *(const float4*)(Bk + (((2 * tx + 1) ^ fk) << 2));
            unsigned long long ap[4];
            ap[0] = a0.x; ap[1] = a0.y; ap[2] = a1.x; ap[3] = a1.y;
            float bv[8];
            bv[0] = b0.x; bv[1] = b0.y; bv[2] = b0.z; bv[3] = b0.w;
            bv[4] = b1.x; bv[5] = b1.y; bv[6] = b1.z; bv[7] = b1.w;
            #pragma unroll
            for (int c = 0; c < 8; c++) {
                unsigned long long bd;
                asm("mov.b64 %0, {%1, %1};" : "=l"(bd) : "f"(bv[c]));
                #pragma unroll
                for (int rp = 0; rp < 4; rp++)
                    asm("fma.rn.f32x2 %0, %1, %2, %0;"
                        : "+l"(acc2[rp * 8 + c]) : "l"(ap[rp]), "l"(bd));
            }
        }
    }
    __syncthreads();

    // epilogue: e = exp(((1+cos)/2 + EPS)/TEMP)  ==  exp2(cos*C1 + C0)
    const float C1f = (float)(0.5 / TEMPC * 1.4426950408889634);
    const float C0f = (float)((0.5 + 1e-8) / TEMPC * 1.4426950408889634);
    const float e0  = exp2fast(C0f);     // value produced by a zero-vector pad column

    float sAllv[8], sMat[8];
    #pragma unroll
    for (int r = 0; r < 8; r++) { sAllv[r] = 0.0f; sMat[r] = 0.0f; }
    int li[8], lj[8];
    #pragma unroll
    for (int r = 0; r < 8; r++) li[r] = sLI[ty * 8 + r];
    #pragma unroll
    for (int c = 0; c < 8; c++) lj[c] = sLJ[tx * 8 + c];
    const bool diagB = (rt == ct);

    #pragma unroll
    for (int rp = 0; rp < 4; rp++) {
        #pragma unroll
        for (int c = 0; c < 8; c++) {
            float lo, hi;
            asm("mov.b64 {%0, %1}, %2;" : "=f"(lo), "=f"(hi) : "l"(acc2[rp * 8 + c]));
            {
                int r = 2 * rp;
                float e = exp2fast(fmaf(lo, C1f, C0f));
                if (diagB && (ty * 8 + r) == (tx * 8 + c)) e = 0.0f;
                sAllv[r] += e;
                if (li[r] == lj[c]) sMat[r] += e;
            }
            {
                int r = 2 * rp + 1;
                float e = exp2fast(fmaf(hi, C1f, C0f));
                if (diagB && (ty * 8 + r) == (tx * 8 + c)) e = 0.0f;
                sAllv[r] += e;
                if (li[r] == lj[c]) sMat[r] += e;
            }
        }
    }

    int npad = (j0 + 128) - MCOLS;
    if (npad < 0) npad = 0;
    float padAdj = (float)npad * e0;

    #pragma unroll
    for (int r = 0; r < 8; r++) {
        float a = sAllv[r], m = sMat[r];
        #pragma unroll
        for (int o = 1; o < 16; o <<= 1) {
            a += __shfl_xor_sync(0xffffffffu, a, o);
            m += __shfl_xor_sync(0xffffffffu, m, o);
        }
        if (tx == 0) {
            int row = i0 + ty * 8 + r;
            g_allp[ct * B_ROWS + row]   = a - padAdj;
            g_matchp[ct * B_ROWS + row] = m;
        }
    }
}

// ---------------- kernel C: per-row loss ----------------
__global__ void k_rows() {
    int i = blockIdx.x * 128 + threadIdx.x;   // grid 64 x 128 = 8192
    float all = 0.0f, match = 0.0f;
    #pragma unroll 5
    for (int ct = 0; ct < NCT; ct++) {
        all   += g_allp[ct * B_ROWS + i];
        match += g_matchp[ct * B_ROWS + i];
    }
    float pos = match;
    float neg = all - match;
    int lab = g_lab[i];
    float cnt = (float)(g_ccount[lab] - 1);
    float prob = pos / (pos + neg);
    prob = prob / (cnt + 1e-8f);
    float lv = -logf(prob + 1e-8f);
    bool msk = lv > 0.3f;
    g_lv[i] = msk ? lv : 0.0f;
    g_lm[i] = msk ? 1.0f : 0.0f;
}

// ---------------- kernel D: final reduction ----------------
__global__ void k_final(float* out) {
    int tid = threadIdx.x;    // 1024 threads
    float s = 0.0f, c = 0.0f;
    for (int i = tid; i < B_ROWS; i += 1024) { s += g_lv[i]; c += g_lm[i]; }
    #pragma unroll
    for (int o = 16; o; o >>= 1) {
        s += __shfl_xor_sync(0xffffffffu, s, o);
        c += __shfl_xor_sync(0xffffffffu, c, o);
    }
    __shared__ float ss[32], sc[32];
    int w = tid >> 5, l = tid & 31;
    if (l == 0) { ss[w] = s; sc[w] = c; }
    __syncthreads();
    if (w == 0) {
        s = ss[l]; c = sc[l];
        #pragma unroll
        for (int o = 16; o; o >>= 1) {
            s += __shfl_xor_sync(0xffffffffu, s, o);
            c += __shfl_xor_sync(0xffffffffu, c, o);
        }
        if (tid == 0) out[0] = s / (c + 1e-8f);
    }
}

extern "C" void kernel_launch(void* const* d_in, const int* in_sizes, int n_in,
                              void* d_out, int out_size) {
    const float* reps    = (const float*)d_in[0];
    const int*   labels  = (const int*)d_in[1];
    const float* centers = (const float*)d_in[2];
    const float* fc_w    = (const float*)d_in[3];
    const float* fc_b    = (const float*)d_in[4];
    float* out = (float*)d_out;

    k_zero<<<1, 32>>>();
    k_prep<<<MPAD, 128>>>(reps, labels, centers, fc_w, fc_b);
    dim3 g(NRT, NCT);
    k_main<<<g, 256>>>();
    k_rows<<<64, 128>>>();
    k_final<<<1, 1024>>>(out);
}

// round 4
// speedup vs baseline: 2.9215x; 2.9215x over previous
#include <cuda_runtime.h>
#include <cuda_bf16.h>
#include <math.h>
#include <stdint.h>

#define B_ROWS 8192
#define MCOLS  8199
#define MPAD   8320
#define H      128
#define EDIM   256
#define NCLS   7
#define NCT    65
#define NTILES 2144

// dynamic smem layout (bytes)
#define OFF_AHI  0
#define OFF_ALO  32768
#define OFF_BHI  65536
#define OFF_BLO  98304
#define OFF_LJ   131072
#define OFF_COLA 131584
#define OFF_COLM 133632
#define OFF_ROWA 135680
#define OFF_ROWM 136704
#define SMEM_BYTES 137728

#define C1F ((float)(0.5 / 0.07 * 1.4426950408889634))
#define C0F ((float)((0.5 + 1e-8) / 0.07 * 1.4426950408889634))

__device__ __nv_bfloat16 g_hi[MPAD * H];
__device__ __nv_bfloat16 g_lo[MPAD * H];
__device__ int   g_lab[MPAD];
__device__ int   g_ccount[NCLS];
__device__ float g_allp[NCT * B_ROWS];
__device__ float g_matchp[NCT * B_ROWS];
__device__ float g_acc[2];

__device__ __forceinline__ float exp2fast(float t) {
    float kf = t + 12582912.0f;
    int   ki = __float_as_int(kf);
    float n  = kf - 12582912.0f;
    float r  = t - n;
    float p  = 0.0013333558f;
    p = fmaf(p, r, 0.0096181291f);
    p = fmaf(p, r, 0.0555041087f);
    p = fmaf(p, r, 0.2402265069f);
    p = fmaf(p, r, 0.6931471806f);
    p = fmaf(p, r, 1.0f);
    return p * __int_as_float((ki << 23) + 0x3f800000);
}

__device__ __forceinline__ uint32_t smem_u32(const void* p) {
    uint32_t a;
    asm("{ .reg .u64 t; cvta.to.shared.u64 t, %1; cvt.u32.u64 %0, t; }" : "=r"(a) : "l"(p));
    return a;
}
__device__ __forceinline__ void cpa16(uint32_t dst, const void* src) {
    asm volatile("cp.async.cg.shared.global [%0], [%1], 16;" :: "r"(dst), "l"(src) : "memory");
}
__device__ __forceinline__ void ldsm4(uint32_t* r, uint32_t addr) {
    asm volatile("ldmatrix.sync.aligned.m8n8.x4.shared.b16 {%0,%1,%2,%3}, [%4];"
                 : "=r"(r[0]), "=r"(r[1]), "=r"(r[2]), "=r"(r[3]) : "r"(addr));
}
__device__ __forceinline__ void mma16816(float* d, const uint32_t* a, uint32_t b0, uint32_t b1) {
    asm volatile(
        "mma.sync.aligned.m16n8k16.row.col.f32.bf16.bf16.f32 "
        "{%0,%1,%2,%3}, {%4,%5,%6,%7}, {%8,%9}, {%0,%1,%2,%3};"
        : "+f"(d[0]), "+f"(d[1]), "+f"(d[2]), "+f"(d[3])
        : "r"(a[0]), "r"(a[1]), "r"(a[2]), "r"(a[3]), "r"(b0), "r"(b1));
}

__global__ void k_zero() {
    if (threadIdx.x < NCLS) g_ccount[threadIdx.x] = 0;
    if (threadIdx.x < 2) g_acc[threadIdx.x] = 0.0f;
}

__global__ void k_prep(const float* __restrict__ reps, const int* __restrict__ labels,
                       const float* __restrict__ centers, const float* __restrict__ fc_w,
                       const float* __restrict__ fc_b) {
    int bid = blockIdx.x;
    int t   = threadIdx.x;   // 0..127
    float x = 0.0f;
    int lab = -1;
    if (bid < B_ROWS) {
        x = reps[bid * H + t];
        lab = labels[bid];
    } else if (bid < MCOLS) {
        int c = bid - B_ROWS;
        float acc = fc_b[t];
        const float* cw = centers + c * EDIM;
        const float* w  = fc_w + t * EDIM;
        #pragma unroll 8
        for (int e = 0; e < EDIM; e++) acc = fmaf(cw[e], w[e], acc);
        x = acc;
        lab = c;
    }
    float s = x * x;
    #pragma unroll
    for (int o = 16; o; o >>= 1) s += __shfl_xor_sync(0xffffffffu, s, o);
    __shared__ float ws[4];
    int w = t >> 5, l = t & 31;
    if (l == 0) ws[w] = s;
    __syncthreads();
    float tot = ws[0] + ws[1] + ws[2] + ws[3];
    float inv = 1.0f / fmaxf(sqrtf(tot), 1e-8f);
    float y = x * inv;
    __nv_bfloat16 hi = __float2bfloat16_rn(y);
    float rem = y - __bfloat162float(hi);
    g_hi[bid * H + t] = hi;
    g_lo[bid * H + t] = __float2bfloat16_rn(rem);
    if (t == 0) {
        g_lab[bid] = lab;
        if (bid < MCOLS) atomicAdd(&g_ccount[lab], 1);
    }
}

__global__ __launch_bounds__(256, 1) void k_main() {
    extern __shared__ char smem[];
    const uint32_t sb = smem_u32(smem);
    const int tid  = threadIdx.x;
    const int wid  = tid >> 5;
    const int lane = tid & 31;
    const int g    = lane >> 2;
    const int tq   = lane & 3;
    const int wr   = wid & 3;     // row-group of warp (32 rows)
    const int wc   = wid >> 1 >> 1;  // column-group (64 cols)

    // decode linear tile index -> (rt, ct), rt <= ct
    int t = blockIdx.x;
    int rt = 0;
    while (t >= NCT - rt) { t -= NCT - rt; rt++; }
    const int ct = rt + t;
    const int i0 = rt * 128;
    const int j0 = ct * 128;
    const bool isDiag  = (rt == ct);
    const bool needCol = (rt != ct) && (ct < 64);

    int* lj = (int*)(smem + OFF_LJ);
    if (tid < 128) lj[tid] = g_lab[j0 + tid];

    // ---- load 4 tiles (A hi/lo from i0, B hi/lo from j0), 128 x 128 bf16 each,
    //      row-major 256B rows, chunk-XOR swizzle for conflict-free ldmatrix ----
    #pragma unroll
    for (int it = 0; it < 32; it++) {
        int idx = tid + it * 256;          // 8192 16B chunks total
        int tile = idx >> 11;              // 0..3
        int w = idx & 2047;
        int row = w >> 4;
        int cch = w & 15;
        const __nv_bfloat16* base =
            (tile == 0) ? g_hi : (tile == 1) ? g_lo : (tile == 2) ? g_hi : g_lo;
        int r0 = (tile < 2) ? i0 : j0;
        const __nv_bfloat16* src = base + (size_t)(r0 + row) * H + cch * 8;
        uint32_t dst = sb + tile * 32768 + row * 256 + ((cch ^ (row & 7)) << 4);
        cpa16(dst, src);
    }
    asm volatile("cp.async.commit_group;" ::: "memory");
    asm volatile("cp.async.wait_group 0;" ::: "memory");
    __syncthreads();

    // ---- 3-pass bf16 MMA: hi*hi + hi*lo + lo*hi ----
    float acc[2][8][4];
    #pragma unroll
    for (int mi = 0; mi < 2; mi++)
        #pragma unroll
        for (int ni = 0; ni < 8; ni++)
            #pragma unroll
            for (int c = 0; c < 4; c++) acc[mi][ni][c] = 0.0f;

    #pragma unroll
    for (int pass = 0; pass < 3; pass++) {
        const uint32_t Ab = sb + ((pass == 2) ? OFF_ALO : OFF_AHI);
        const uint32_t Bb = sb + ((pass == 1) ? OFF_BLO : OFF_BHI);
        #pragma unroll
        for (int ks = 0; ks < 8; ks++) {
            uint32_t a[2][4];
            #pragma unroll
            for (int mi = 0; mi < 2; mi++) {
                int row = wr * 32 + mi * 16 + (lane & 15);
                int kch = ks * 2 + (lane >> 4);
                ldsm4(a[mi], Ab + row * 256 + ((kch ^ (row & 7)) << 4));
            }
            uint32_t b[4][4];
            #pragma unroll
            for (int nq = 0; nq < 4; nq++) {
                int rowN = wc * 64 + nq * 16 + (lane & 7) + ((lane >> 4) << 3);
                int kch = ks * 2 + ((lane >> 3) & 1);
                ldsm4(b[nq], Bb + rowN * 256 + ((kch ^ (rowN & 7)) << 4));
            }
            #pragma unroll
            for (int mi = 0; mi < 2; mi++)
                #pragma unroll
                for (int ni = 0; ni < 8; ni++)
                    mma16816(acc[mi][ni], a[mi],
                             b[ni >> 1][(ni & 1) * 2], b[ni >> 1][(ni & 1) * 2 + 1]);
        }
    }
    __syncthreads();

    // ---- epilogue: e = exp2(cos*C1 + C0); row sums + (mirror) col sums ----
    int li4[4];
    #pragma unroll
    for (int k = 0; k < 4; k++)   // k = mi*2+ch  -> row wr*32 + mi*16 + ch*8 + g
        li4[k] = g_lab[i0 + wr * 32 + (k >> 1) * 16 + (k & 1) * 8 + g];
    int ljr[8][2];
    #pragma unroll
    for (int ni = 0; ni < 8; ni++) {
        ljr[ni][0] = lj[wc * 64 + ni * 8 + tq * 2 + 0];
        ljr[ni][1] = lj[wc * 64 + ni * 8 + tq * 2 + 1];
    }

    float rs[4], rm[4], cs[8][2], cm[8][2];
    #pragma unroll
    for (int k = 0; k < 4; k++) { rs[k] = 0.0f; rm[k] = 0.0f; }
    #pragma unroll
    for (int ni = 0; ni < 8; ni++) { cs[ni][0] = cs[ni][1] = 0.0f; cm[ni][0] = cm[ni][1] = 0.0f; }

    #pragma unroll
    for (int mi = 0; mi < 2; mi++)
        #pragma unroll
        for (int ni = 0; ni < 8; ni++)
            #pragma unroll
            for (int c = 0; c < 4; c++) {
                int ch = c >> 1, cl = c & 1;
                int R = wr * 32 + mi * 16 + ch * 8 + g;
                int C = wc * 64 + ni * 8 + tq * 2 + cl;
                float e = exp2fast(fmaf(acc[mi][ni][c], C1F, C0F));
                if (isDiag && R == C) e = 0.0f;
                float m = (li4[mi * 2 + ch] == ljr[ni][cl]) ? e : 0.0f;
                rs[mi * 2 + ch] += e;
                rm[mi * 2 + ch] += m;
                cs[ni][cl] += e;
                cm[ni][cl] += m;
            }

    // fold row sums over tq (cols)
    #pragma unroll
    for (int k = 0; k < 4; k++) {
        #pragma unroll
        for (int o = 1; o <= 2; o <<= 1) {
            rs[k] += __shfl_xor_sync(0xffffffffu, rs[k], o);
            rm[k] += __shfl_xor_sync(0xffffffffu, rm[k], o);
        }
    }
    float* rowA = (float*)(smem + OFF_ROWA);
    float* rowM = (float*)(smem + OFF_ROWM);
    if (tq == 0) {
        #pragma unroll
        for (int k = 0; k < 4; k++) {
            int R = wr * 32 + (k >> 1) * 16 + (k & 1) * 8 + g;
            rowA[wc * 128 + R] = rs[k];
            rowM[wc * 128 + R] = rm[k];
        }
    }

    // fold col sums over g (rows)
    if (needCol) {
        #pragma unroll
        for (int ni = 0; ni < 8; ni++)
            #pragma unroll
            for (int cl = 0; cl < 2; cl++) {
                #pragma unroll
                for (int o = 4; o <= 16; o <<= 1) {
                    cs[ni][cl] += __shfl_xor_sync(0xffffffffu, cs[ni][cl], o);
                    cm[ni][cl] += __shfl_xor_sync(0xffffffffu, cm[ni][cl], o);
                }
            }
        float* colA = (float*)(smem + OFF_COLA);
        float* colM = (float*)(smem + OFF_COLM);
        if (g == 0) {
            #pragma unroll
            for (int ni = 0; ni < 8; ni++)
                #pragma unroll
                for (int cl = 0; cl < 2; cl++) {
                    int C = wc * 64 + ni * 8 + tq * 2 + cl;
                    colA[wr * 128 + C] = cs[ni][cl];
                    colM[wr * 128 + C] = cm[ni][cl];
                }
        }
    }
    __syncthreads();

    if (tid < 128) {
        float a = rowA[tid] + rowA[128 + tid];
        float m = rowM[tid] + rowM[128 + tid];
        if (ct == 64) a -= (float)(MPAD - MCOLS) * exp2fast(C0F);
        g_allp[ct * B_ROWS + i0 + tid]   = a;
        g_matchp[ct * B_ROWS + i0 + tid] = m;
        if (needCol) {
            float* colA = (float*)(smem + OFF_COLA);
            float* colM = (float*)(smem + OFF_COLM);
            float ca = colA[tid] + colA[128 + tid] + colA[256 + tid] + colA[384 + tid];
            float cmv = colM[tid] + colM[128 + tid] + colM[256 + tid] + colM[384 + tid];
            g_allp[rt * B_ROWS + j0 + tid]   = ca;
            g_matchp[rt * B_ROWS + j0 + tid] = cmv;
        }
    }
}

// per-row loss + block reduce + atomic accumulate
__global__ void k_rows() {
    int tid = threadIdx.x;           // 128
    int q = tid >> 5, r = tid & 31;
    int i = blockIdx.x * 32 + r;     // 256 blocks
    float all = 0.0f, match = 0.0f;
    int c0 = q * 17;
    int cn = (q < 3) ? 17 : 14;
    for (int k = 0; k < cn; k++) {
        int ctk = c0 + k;
        all   += g_allp[ctk * B_ROWS + i];
        match += g_matchp[ctk * B_ROWS + i];
    }
    __shared__ float sa[4][32], smm[4][32];
    sa[q][r] = all; smm[q][r] = match;
    __syncthreads();
    if (q == 0) {
        all   = sa[0][r] + sa[1][r] + sa[2][r] + sa[3][r];
        match = smm[0][r] + smm[1][r] + smm[2][r] + smm[3][r];
        float pos = match;
        float neg = all - match;
        int lab = g_lab[i];
        float cnt = (float)(g_ccount[lab] - 1);
        float prob = pos / (pos + neg);
        prob = prob / (cnt + 1e-8f);
        float lv = -logf(prob + 1e-8f);
        bool msk = lv > 0.3f;
        float lsum = msk ? lv : 0.0f;
        float lcnt = msk ? 1.0f : 0.0f;
        #pragma unroll
        for (int o = 16; o; o >>= 1) {
            lsum += __shfl_xor_sync(0xffffffffu, lsum, o);
            lcnt += __shfl_xor_sync(0xffffffffu, lcnt, o);
        }
        if (r == 0) {
            atomicAdd(&g_acc[0], lsum);
            atomicAdd(&g_acc[1], lcnt);
        }
    }
}

__global__ void k_final(float* out) {
    out[0] = g_acc[0] / (g_acc[1] + 1e-8f);
}

extern "C" void kernel_launch(void* const* d_in, const int* in_sizes, int n_in,
                              void* d_out, int out_size) {
    const float* reps    = (const float*)d_in[0];
    const int*   labels  = (const int*)d_in[1];
    const float* centers = (const float*)d_in[2];
    const float* fc_w    = (const float*)d_in[3];
    const float* fc_b    = (const float*)d_in[4];
    float* out = (float*)d_out;

    static int configured = 0;
    if (!configured) {
        cudaFuncSetAttribute(k_main, cudaFuncAttributeMaxDynamicSharedMemorySize, SMEM_BYTES);
        configured = 1;
    }

    k_zero<<<1, 32>>>();
    k_prep<<<MPAD, 128>>>(reps, labels, centers, fc_w, fc_b);
    k_main<<<NTILES, 256, SMEM_BYTES>>>();
    k_rows<<<256, 128>>>();
    k_final<<<1, 1>>>(out);
}

// round 6
// speedup vs baseline: 3.0963x; 1.0598x over previous
#include <cuda_runtime.h>
#include <cuda_bf16.h>
#include <math.h>
#include <stdint.h>

#define B_ROWS 8192
#define MCOLS  8199
#define MPAD   8320
#define H      128
#define EDIM   256
#define NCLS   7
#define NCT    65
#define NTILES 2144
#define NBLK   148

// dynamic smem layout (bytes)
#define OFF_A    0          // A hi (32768) + A lo (32768)
#define OFF_B0   65536      // B buf0 hi+lo
#define OFF_B1   131072     // B buf1 hi+lo
#define OFF_LJ   196608
#define OFF_ROWA 197120
#define OFF_ROWM 198144
#define OFF_COLA 199168
#define OFF_COLM 201216
#define SMEM_BYTES 203264

#define C1F ((float)(0.5 / 0.07 * 1.4426950408889634))
#define C0F ((float)((0.5 + 1e-8) / 0.07 * 1.4426950408889634))

__device__ __nv_bfloat16 g_hi[MPAD * H];
__device__ __nv_bfloat16 g_lo[MPAD * H];
__device__ int   g_lab[MPAD];
__device__ int   g_ccount[NCLS];
__device__ float g_allp[NCT * B_ROWS];
__device__ float g_matchp[NCT * B_ROWS];
__device__ float g_acc[2];

__device__ __forceinline__ float exp2fast(float t) {
    float kf = t + 12582912.0f;
    int   ki = __float_as_int(kf);
    float n  = kf - 12582912.0f;
    float r  = t - n;
    float p  = 0.0013333558f;
    p = fmaf(p, r, 0.0096181291f);
    p = fmaf(p, r, 0.0555041087f);
    p = fmaf(p, r, 0.2402265069f);
    p = fmaf(p, r, 0.6931471806f);
    p = fmaf(p, r, 1.0f);
    return p * __int_as_float((ki << 23) + 0x3f800000);
}

__device__ __forceinline__ uint32_t smem_u32(const void* p) {
    uint32_t a;
    asm("{ .reg .u64 t; cvta.to.shared.u64 t, %1; cvt.u32.u64 %0, t; }" : "=r"(a) : "l"(p));
    return a;
}
__device__ __forceinline__ void cpa16(uint32_t dst, const void* src) {
    asm volatile("cp.async.cg.shared.global [%0], [%1], 16;" :: "r"(dst), "l"(src) : "memory");
}
__device__ __forceinline__ void ldsm4(uint32_t* r, uint32_t addr) {
    asm volatile("ldmatrix.sync.aligned.m8n8.x4.shared.b16 {%0,%1,%2,%3}, [%4];"
                 : "=r"(r[0]), "=r"(r[1]), "=r"(r[2]), "=r"(r[3]) : "r"(addr));
}
__device__ __forceinline__ void mma16816(float* d, const uint32_t* a, uint32_t b0, uint32_t b1) {
    asm volatile(
        "mma.sync.aligned.m16n8k16.row.col.f32.bf16.bf16.f32 "
        "{%0,%1,%2,%3}, {%4,%5,%6,%7}, {%8,%9}, {%0,%1,%2,%3};"
        : "+f"(d[0]), "+f"(d[1]), "+f"(d[2]), "+f"(d[3])
        : "r"(a[0]), "r"(a[1]), "r"(a[2]), "r"(a[3]), "r"(b0), "r"(b1));
}

// load one 128x128 bf16 hi+lo tile pair (64KB) into dstBase, chunk-XOR swizzled
__device__ __forceinline__ void load_tile(uint32_t dstBase, int r0, int tid) {
    #pragma unroll
    for (int it = 0; it < 16; it++) {
        int idx = tid + it * 256;          // 4096 16B chunks
        int prec = idx >> 11;              // 0 hi, 1 lo
        int w = idx & 2047;
        int row = w >> 4;
        int cch = w & 15;
        const __nv_bfloat16* base = prec ? g_lo : g_hi;
        const __nv_bfloat16* src = base + (size_t)(r0 + row) * H + cch * 8;
        uint32_t dst = dstBase + prec * 32768 + row * 256 + ((cch ^ (row & 7)) << 4);
        cpa16(dst, src);
    }
}

__global__ void k_zero() {
    if (threadIdx.x < NCLS) g_ccount[threadIdx.x] = 0;
    if (threadIdx.x < 2) g_acc[threadIdx.x] = 0.0f;
}

__global__ void k_prep(const float* __restrict__ reps, const int* __restrict__ labels,
                       const float* __restrict__ centers, const float* __restrict__ fc_w,
                       const float* __restrict__ fc_b) {
    int bid = blockIdx.x;
    int t   = threadIdx.x;   // 0..127
    float x = 0.0f;
    int lab = -1;
    if (bid < B_ROWS) {
        x = reps[bid * H + t];
        lab = labels[bid];
    } else if (bid < MCOLS) {
        int c = bid - B_ROWS;
        float acc = fc_b[t];
        const float* cw = centers + c * EDIM;
        const float* w  = fc_w + t * EDIM;
        #pragma unroll 8
        for (int e = 0; e < EDIM; e++) acc = fmaf(cw[e], w[e], acc);
        x = acc;
        lab = c;
    }
    float s = x * x;
    #pragma unroll
    for (int o = 16; o; o >>= 1) s += __shfl_xor_sync(0xffffffffu, s, o);
    __shared__ float ws[4];
    int w = t >> 5, l = t & 31;
    if (l == 0) ws[w] = s;
    __syncthreads();
    float tot = ws[0] + ws[1] + ws[2] + ws[3];
    float inv = 1.0f / fmaxf(sqrtf(tot), 1e-8f);
    float y = x * inv;
    __nv_bfloat16 hi = __float2bfloat16_rn(y);
    float rem = y - __bfloat162float(hi);
    g_hi[bid * H + t] = hi;
    g_lo[bid * H + t] = __float2bfloat16_rn(rem);
    if (t == 0) {
        g_lab[bid] = lab;
        if (bid < MCOLS) atomicAdd(&g_ccount[lab], 1);
    }
}

__global__ __launch_bounds__(256, 1) void k_main() {
    extern __shared__ char smem[];
    const uint32_t sb = smem_u32(smem);
    const int tid  = threadIdx.x;
    const int wid  = tid >> 5;
    const int lane = tid & 31;
    const int g    = lane >> 2;
    const int tq   = lane & 3;
    const int wr   = wid & 3;      // row-group of warp (32 rows)
    const int wc   = wid >> 2;     // column-group (64 cols)

    // contiguous chunk of tiles for this CTA (tiles sorted by rt then ct)
    const int bid = blockIdx.x;
    const int start = bid * 14 + (bid < 72 ? bid : 72);
    const int cnt = 14 + (bid < 72 ? 1 : 0);

    // decode start -> (rt, ct), rt <= ct
    int t = start, rt = 0;
    while (t >= NCT - rt) { t -= NCT - rt; rt++; }
    int ct = rt + t;

    int* lj = (int*)(smem + OFF_LJ);
    float* rowA = (float*)(smem + OFF_ROWA);
    float* rowM = (float*)(smem + OFF_ROWM);
    float* colA = (float*)(smem + OFF_COLA);
    float* colM = (float*)(smem + OFF_COLM);

    // bootstrap: load A(rt) and B(ct) into buf0
    load_tile(sb + OFF_A, rt * 128, tid);
    load_tile(sb + OFF_B0, ct * 128, tid);
    asm volatile("cp.async.commit_group;" ::: "memory");
    int buf = 0;

    for (int k = 0; k < cnt; k++) {
        const int i0 = rt * 128;
        const int j0 = ct * 128;
        const bool isDiag  = (rt == ct);
        const bool needCol = (!isDiag) && (ct < 64);
        // next tile coords
        int nrt = rt, nct = ct + 1;
        if (nct >= NCT) { nrt = rt + 1; nct = nrt; }

        asm volatile("cp.async.wait_group 0;" ::: "memory");
        __syncthreads();                                   // S0: B(k) (+A) visible

        if (tid < 128) lj[tid] = g_lab[j0 + tid];
        // prefetch next B into the other buffer (overlaps with MMA+epilogue)
        if (k + 1 < cnt) {
            load_tile(sb + OFF_B0 + (buf ^ 1) * 65536, nct * 128, tid);
            asm volatile("cp.async.commit_group;" ::: "memory");
        }

        // ---- 3-pass bf16 MMA: hi*hi + hi*lo + lo*hi ----
        float acc[2][8][4];
        #pragma unroll
        for (int mi = 0; mi < 2; mi++)
            #pragma unroll
            for (int ni = 0; ni < 8; ni++)
                #pragma unroll
                for (int c = 0; c < 4; c++) acc[mi][ni][c] = 0.0f;

        const uint32_t Bbuf = sb + OFF_B0 + buf * 65536;
        #pragma unroll
        for (int pass = 0; pass < 3; pass++) {
            const uint32_t Ab = sb + OFF_A + ((pass == 2) ? 32768 : 0);
            const uint32_t Bb = Bbuf + ((pass == 1) ? 32768 : 0);
            #pragma unroll
            for (int ks = 0; ks < 8; ks++) {
                uint32_t a[2][4];
                #pragma unroll
                for (int mi = 0; mi < 2; mi++) {
                    int row = wr * 32 + mi * 16 + (lane & 15);
                    int kch = ks * 2 + (lane >> 4);
                    ldsm4(a[mi], Ab + row * 256 + ((kch ^ (row & 7)) << 4));
                }
                uint32_t b[4][4];
                #pragma unroll
                for (int nq = 0; nq < 4; nq++) {
                    int rowN = wc * 64 + nq * 16 + (lane & 7) + ((lane >> 4) << 3);
                    int kch = ks * 2 + ((lane >> 3) & 1);
                    ldsm4(b[nq], Bb + rowN * 256 + ((kch ^ (rowN & 7)) << 4));
                }
                #pragma unroll
                for (int mi = 0; mi < 2; mi++)
                    #pragma unroll
                    for (int ni = 0; ni < 8; ni++)
                        mma16816(acc[mi][ni], a[mi],
                                 b[ni >> 1][(ni & 1) * 2], b[ni >> 1][(ni & 1) * 2 + 1]);
            }
        }
        __syncthreads();                                   // S1: MMA done, lj visible

        // ---- epilogue ----
        int li4[4];
        #pragma unroll
        for (int kk = 0; kk < 4; kk++)
            li4[kk] = g_lab[i0 + wr * 32 + (kk >> 1) * 16 + (kk & 1) * 8 + g];
        int ljr[8][2];
        #pragma unroll
        for (int ni = 0; ni < 8; ni++) {
            ljr[ni][0] = lj[wc * 64 + ni * 8 + tq * 2 + 0];
            ljr[ni][1] = lj[wc * 64 + ni * 8 + tq * 2 + 1];
        }

        float rs[4], rm[4], cs[8][2], cm[8][2];
        #pragma unroll
        for (int kk = 0; kk < 4; kk++) { rs[kk] = 0.0f; rm[kk] = 0.0f; }
        #pragma unroll
        for (int ni = 0; ni < 8; ni++) { cs[ni][0] = cs[ni][1] = 0.0f; cm[ni][0] = cm[ni][1] = 0.0f; }

        #pragma unroll
        for (int mi = 0; mi < 2; mi++)
            #pragma unroll
            for (int ni = 0; ni < 8; ni++)
                #pragma unroll
                for (int c = 0; c < 4; c++) {
                    int ch = c >> 1, cl = c & 1;
                    int R = wr * 32 + mi * 16 + ch * 8 + g;
                    int C = wc * 64 + ni * 8 + tq * 2 + cl;
                    float e = exp2fast(fmaf(acc[mi][ni][c], C1F, C0F));
                    if (isDiag && R == C) e = 0.0f;
                    float m = (li4[mi * 2 + ch] == ljr[ni][cl]) ? e : 0.0f;
                    rs[mi * 2 + ch] += e;
                    rm[mi * 2 + ch] += m;
                    cs[ni][cl] += e;
                    cm[ni][cl] += m;
                }

        #pragma unroll
        for (int kk = 0; kk < 4; kk++) {
            #pragma unroll
            for (int o = 1; o <= 2; o <<= 1) {
                rs[kk] += __shfl_xor_sync(0xffffffffu, rs[kk], o);
                rm[kk] += __shfl_xor_sync(0xffffffffu, rm[kk], o);
            }
        }
        if (tq == 0) {
            #pragma unroll
            for (int kk = 0; kk < 4; kk++) {
                int R = wr * 32 + (kk >> 1) * 16 + (kk & 1) * 8 + g;
                rowA[wc * 128 + R] = rs[kk];
                rowM[wc * 128 + R] = rm[kk];
            }
        }

        if (needCol) {
            #pragma unroll
            for (int ni = 0; ni < 8; ni++)
                #pragma unroll
                for (int cl = 0; cl < 2; cl++) {
                    #pragma unroll
                    for (int o = 4; o <= 16; o <<= 1) {
                        cs[ni][cl] += __shfl_xor_sync(0xffffffffu, cs[ni][cl], o);
                        cm[ni][cl] += __shfl_xor_sync(0xffffffffu, cm[ni][cl], o);
                    }
                }
            if (g == 0) {
                #pragma unroll
                for (int ni = 0; ni < 8; ni++)
                    #pragma unroll
                    for (int cl = 0; cl < 2; cl++) {
                        int C = wc * 64 + ni * 8 + tq * 2 + cl;
                        colA[wr * 128 + C] = cs[ni][cl];
                        colM[wr * 128 + C] = cm[ni][cl];
                    }
            }
        }
        __syncthreads();                                   // S2

        if (tid < 128) {
            float a = rowA[tid] + rowA[128 + tid];
            float m = rowM[tid] + rowM[128 + tid];
            if (ct == 64) a -= (float)(MPAD - MCOLS) * exp2fast(C0F);
            g_allp[ct * B_ROWS + i0 + tid]   = a;
            g_matchp[ct * B_ROWS + i0 + tid] = m;
            if (needCol) {
                float ca  = colA[tid] + colA[128 + tid] + colA[256 + tid] + colA[384 + tid];
                float cmv = colM[tid] + colM[128 + tid] + colM[256 + tid] + colM[384 + tid];
                g_allp[rt * B_ROWS + j0 + tid]   = ca;
                g_matchp[rt * B_ROWS + j0 + tid] = cmv;
            }
        }

        // row-block boundary: reload A (rare; MMA reads of A are done past S1)
        if (k + 1 < cnt && nrt != rt) {
            load_tile(sb + OFF_A, nrt * 128, tid);
            asm volatile("cp.async.commit_group;" ::: "memory");
        }
        rt = nrt; ct = nct; buf ^= 1;
    }
}

// per-row loss + block reduce + atomic accumulate
__global__ void k_rows() {
    int tid = threadIdx.x;           // 128
    int q = tid >> 5, r = tid & 31;
    int i = blockIdx.x * 32 + r;     // 256 blocks
    float all = 0.0f, match = 0.0f;
    int c0 = q * 17;
    int cn = (q < 3) ? 17 : 14;
    for (int k = 0; k < cn; k++) {
        int ctk = c0 + k;
        all   += g_allp[ctk * B_ROWS + i];
        match += g_matchp[ctk * B_ROWS + i];
    }
    __shared__ float sa[4][32], smm[4][32];
    sa[q][r] = all; smm[q][r] = match;
    __syncthreads();
    if (q == 0) {
        all   = sa[0][r] + sa[1][r] + sa[2][r] + sa[3][r];
        match = smm[0][r] + smm[1][r] + smm[2][r] + smm[3][r];
        float pos = match;
        float neg = all - match;
        int lab = g_lab[i];
        float cnt = (float)(g_ccount[lab] - 1);
        float prob = pos / (pos + neg);
        prob = prob / (cnt + 1e-8f);
        float lv = -logf(prob + 1e-8f);
        bool msk = lv > 0.3f;
        float lsum = msk ? lv : 0.0f;
        float lcnt = msk ? 1.0f : 0.0f;
        #pragma unroll
        for (int o = 16; o; o >>= 1) {
            lsum += __shfl_xor_sync(0xffffffffu, lsum, o);
            lcnt += __shfl_xor_sync(0xffffffffu, lcnt, o);
        }
        if (r == 0) {
            atomicAdd(&g_acc[0], lsum);
            atomicAdd(&g_acc[1], lcnt);
        }
    }
}

__global__ void k_final(float* out) {
    out[0] = g_acc[0] / (g_acc[1] + 1e-8f);
}

extern "C" void kernel_launch(void* const* d_in, const int* in_sizes, int n_in,
                              void* d_out, int out_size) {
    const float* reps    = (const float*)d_in[0];
    const int*   labels  = (const int*)d_in[1];
    const float* centers = (const float*)d_in[2];
    const float* fc_w    = (const float*)d_in[3];
    const float* fc_b    = (const float*)d_in[4];
    float* out = (float*)d_out;

    static int configured = 0;
    if (!configured) {
        cudaFuncSetAttribute(k_main, cudaFuncAttributeMaxDynamicSharedMemorySize, SMEM_BYTES);
        configured = 1;
    }

    k_zero<<<1, 32>>>();
    k_prep<<<MPAD, 128>>>(reps, labels, centers, fc_w, fc_b);
    k_main<<<NBLK, 256, SMEM_BYTES>>>();
    k_rows<<<256, 128>>>();
    k_final<<<1, 1>>>(out);
}

// round 11
// speedup vs baseline: 4.8793x; 1.5759x over previous
#include <cuda_runtime.h>
#include <cuda_fp16.h>
#include <math.h>
#include <stdint.h>

#define B_ROWS 8192
#define MCOLS  8199
#define MPAD   8320
#define H      128
#define EDIM   256
#define NCLS   7
#define NCT    65
#define NTILES 2144
#define NBLK   148

// dynamic smem layout (bytes)
#define OFF_A    0          // A tile fp16 (32768)
#define OFF_B0   32768      // B buf0 (32768)
#define OFF_B1   65536      // B buf1 (32768)
#define OFF_LJ   98304
#define OFF_ROWA 98816
#define OFF_ROWM 99840
#define OFF_COLA 100864
#define OFF_COLM 102912
#define SMEM_BYTES 104960

#define C1F ((float)(0.5 / 0.07 * 1.4426950408889634))
#define C0F ((float)((0.5 + 1e-8) / 0.07 * 1.4426950408889634))

__device__ __half g_h[MPAD * H];
__device__ int   g_lab[MPAD];
__device__ int   g_ccount[NCLS];
__device__ float g_allp[NCT * B_ROWS];
__device__ float g_matchp[NCT * B_ROWS];
__device__ float g_acc[2];

__device__ __forceinline__ float exp2fast(float t) {
    float kf = t + 12582912.0f;
    int   ki = __float_as_int(kf);
    float n  = kf - 12582912.0f;
    float r  = t - n;
    float p  = 0.0013333558f;
    p = fmaf(p, r, 0.0096181291f);
    p = fmaf(p, r, 0.0555041087f);
    p = fmaf(p, r, 0.2402265069f);
    p = fmaf(p, r, 0.6931471806f);
    p = fmaf(p, r, 1.0f);
    return p * __int_as_float((ki << 23) + 0x3f800000);
}

__device__ __forceinline__ uint32_t smem_u32(const void* p) {
    uint32_t a;
    asm("{ .reg .u64 t; cvta.to.shared.u64 t, %1; cvt.u32.u64 %0, t; }" : "=r"(a) : "l"(p));
    return a;
}
__device__ __forceinline__ void cpa16(uint32_t dst, const void* src) {
    asm volatile("cp.async.cg.shared.global [%0], [%1], 16;" :: "r"(dst), "l"(src) : "memory");
}
__device__ __forceinline__ void ldsm4(uint32_t* r, uint32_t addr) {
    asm volatile("ldmatrix.sync.aligned.m8n8.x4.shared.b16 {%0,%1,%2,%3}, [%4];"
                 : "=r"(r[0]), "=r"(r[1]), "=r"(r[2]), "=r"(r[3]) : "r"(addr));
}
__device__ __forceinline__ void mma16816(float* d, const uint32_t* a, uint32_t b0, uint32_t b1) {
    asm volatile(
        "mma.sync.aligned.m16n8k16.row.col.f32.f16.f16.f32 "
        "{%0,%1,%2,%3}, {%4,%5,%6,%7}, {%8,%9}, {%0,%1,%2,%3};"
        : "+f"(d[0]), "+f"(d[1]), "+f"(d[2]), "+f"(d[3])
        : "r"(a[0]), "r"(a[1]), "r"(a[2]), "r"(a[3]), "r"(b0), "r"(b1));
}

// load one 128x128 fp16 tile (32KB), chunk-XOR swizzled
__device__ __forceinline__ void load_tile(uint32_t dstBase, int r0, int tid) {
    #pragma unroll
    for (int it = 0; it < 8; it++) {
        int idx = tid + it * 256;          // 2048 16B chunks
        int row = idx >> 4;
        int cch = idx & 15;
        const __half* src = g_h + (size_t)(r0 + row) * H + cch * 8;
        uint32_t dst = dstBase + row * 256 + ((cch ^ (row & 7)) << 4);
        cpa16(dst, src);
    }
}

__global__ void k_prep(const float* __restrict__ reps, const int* __restrict__ labels,
                       const float* __restrict__ centers, const float* __restrict__ fc_w,
                       const float* __restrict__ fc_b) {
    int bid = blockIdx.x;
    int t   = threadIdx.x;   // 0..127
    float x = 0.0f;
    int lab = -1;
    if (bid < B_ROWS) {
        x = reps[bid * H + t];
        lab = labels[bid];
    } else if (bid < MCOLS) {
        int c = bid - B_ROWS;
        float acc = fc_b[t];
        const float* cw = centers + c * EDIM;
        const float* w  = fc_w + t * EDIM;
        #pragma unroll 8
        for (int e = 0; e < EDIM; e++) acc = fmaf(cw[e], w[e], acc);
        x = acc;
        lab = c;
    }
    float s = x * x;
    #pragma unroll
    for (int o = 16; o; o >>= 1) s += __shfl_xor_sync(0xffffffffu, s, o);
    __shared__ float ws[4];
    int w = t >> 5, l = t & 31;
    if (l == 0) ws[w] = s;
    __syncthreads();
    float tot = ws[0] + ws[1] + ws[2] + ws[3];
    float inv = 1.0f / fmaxf(sqrtf(tot), 1e-8f);
    g_h[bid * H + t] = __float2half_rn(x * inv);
    if (t == 0) {
        g_lab[bid] = lab;
        if (bid < MCOLS) atomicAdd(&g_ccount[lab], 1);
    }
}

__global__ __launch_bounds__(256, 1) void k_main() {
    extern __shared__ char smem[];
    const uint32_t sb = smem_u32(smem);
    const int tid  = threadIdx.x;
    const int wid  = tid >> 5;
    const int lane = tid & 31;
    const int g    = lane >> 2;
    const int tq   = lane & 3;
    const int wr   = wid & 3;      // row-group (32 rows)
    const int wc   = wid >> 2;     // column-group (64 cols)

    const int bid = blockIdx.x;
    const int start = bid * 14 + (bid < 72 ? bid : 72);
    const int cnt = 14 + (bid < 72 ? 1 : 0);

    int t = start, rt = 0;
    while (t >= NCT - rt) { t -= NCT - rt; rt++; }
    int ct = rt + t;

    int* lj = (int*)(smem + OFF_LJ);
    float* rowA = (float*)(smem + OFF_ROWA);
    float* rowM = (float*)(smem + OFF_ROWM);
    float* colA = (float*)(smem + OFF_COLA);
    float* colM = (float*)(smem + OFF_COLM);

    load_tile(sb + OFF_A, rt * 128, tid);
    load_tile(sb + OFF_B0, ct * 128, tid);
    asm volatile("cp.async.commit_group;" ::: "memory");
    int buf = 0;

    for (int k = 0; k < cnt; k++) {
        const int i0 = rt * 128;
        const int j0 = ct * 128;
        const bool isDiag  = (rt == ct);
        const bool needCol = (!isDiag) && (ct < 64);
        int nrt = rt, nct = ct + 1;
        if (nct >= NCT) { nrt = rt + 1; nct = nrt; }

        asm volatile("cp.async.wait_group 0;" ::: "memory");
        __syncthreads();                                   // S0: tiles visible

        if (tid < 128) lj[tid] = g_lab[j0 + tid];
        if (k + 1 < cnt) {
            load_tile(sb + OFF_B0 + (buf ^ 1) * 32768, nct * 128, tid);
            asm volatile("cp.async.commit_group;" ::: "memory");
        }

        // ---- single-pass fp16 MMA ----
        float acc[2][8][4];
        #pragma unroll
        for (int mi = 0; mi < 2; mi++)
            #pragma unroll
            for (int ni = 0; ni < 8; ni++)
                #pragma unroll
                for (int c = 0; c < 4; c++) acc[mi][ni][c] = 0.0f;

        const uint32_t Ab = sb + OFF_A;
        const uint32_t Bb = sb + OFF_B0 + buf * 32768;
        #pragma unroll
        for (int ks = 0; ks < 8; ks++) {
            uint32_t a[2][4];
            #pragma unroll
            for (int mi = 0; mi < 2; mi++) {
                int row = wr * 32 + mi * 16 + (lane & 15);
                int kch = ks * 2 + (lane >> 4);
                ldsm4(a[mi], Ab + row * 256 + ((kch ^ (row & 7)) << 4));
            }
            uint32_t b[4][4];
            #pragma unroll
            for (int nq = 0; nq < 4; nq++) {
                int rowN = wc * 64 + nq * 16 + (lane & 7) + ((lane >> 4) << 3);
                int kch = ks * 2 + ((lane >> 3) & 1);
                ldsm4(b[nq], Bb + rowN * 256 + ((kch ^ (rowN & 7)) << 4));
            }
            #pragma unroll
            for (int mi = 0; mi < 2; mi++)
                #pragma unroll
                for (int ni = 0; ni < 8; ni++)
                    mma16816(acc[mi][ni], a[mi],
                             b[ni >> 1][(ni & 1) * 2], b[ni >> 1][(ni & 1) * 2 + 1]);
        }
        __syncthreads();                                   // S1: MMA done, lj visible

        // ---- epilogue ----
        int li4[4];
        #pragma unroll
        for (int kk = 0; kk < 4; kk++)
            li4[kk] = g_lab[i0 + wr * 32 + (kk >> 1) * 16 + (kk & 1) * 8 + g];
        int ljr[8][2];
        #pragma unroll
        for (int ni = 0; ni < 8; ni++) {
            ljr[ni][0] = lj[wc * 64 + ni * 8 + tq * 2 + 0];
            ljr[ni][1] = lj[wc * 64 + ni * 8 + tq * 2 + 1];
        }

        float rs[4], rm[4], cs[8][2], cm[8][2];
        #pragma unroll
        for (int kk = 0; kk < 4; kk++) { rs[kk] = 0.0f; rm[kk] = 0.0f; }
        #pragma unroll
        for (int ni = 0; ni < 8; ni++) { cs[ni][0] = cs[ni][1] = 0.0f; cm[ni][0] = cm[ni][1] = 0.0f; }

        #pragma unroll
        for (int mi = 0; mi < 2; mi++)
            #pragma unroll
            for (int ni = 0; ni < 8; ni++)
                #pragma unroll
                for (int c = 0; c < 4; c++) {
                    int ch = c >> 1, cl = c & 1;
                    int R = wr * 32 + mi * 16 + ch * 8 + g;
                    int C = wc * 64 + ni * 8 + tq * 2 + cl;
                    float e = exp2fast(fmaf(acc[mi][ni][c], C1F, C0F));
                    if (isDiag && R == C) e = 0.0f;
                    float m = (li4[mi * 2 + ch] == ljr[ni][cl]) ? e : 0.0f;
                    rs[mi * 2 + ch] += e;
                    rm[mi * 2 + ch] += m;
                    cs[ni][cl] += e;
                    cm[ni][cl] += m;
                }

        #pragma unroll
        for (int kk = 0; kk < 4; kk++) {
            #pragma unroll
            for (int o = 1; o <= 2; o <<= 1) {
                rs[kk] += __shfl_xor_sync(0xffffffffu, rs[kk], o);
                rm[kk] += __shfl_xor_sync(0xffffffffu, rm[kk], o);
            }
        }
        if (tq == 0) {
            #pragma unroll
            for (int kk = 0; kk < 4; kk++) {
                int R = wr * 32 + (kk >> 1) * 16 + (kk & 1) * 8 + g;
                rowA[wc * 128 + R] = rs[kk];
                rowM[wc * 128 + R] = rm[kk];
            }
        }

        if (needCol) {
            #pragma unroll
            for (int ni = 0; ni < 8; ni++)
                #pragma unroll
                for (int cl = 0; cl < 2; cl++) {
                    #pragma unroll
                    for (int o = 4; o <= 16; o <<= 1) {
                        cs[ni][cl] += __shfl_xor_sync(0xffffffffu, cs[ni][cl], o);
                        cm[ni][cl] += __shfl_xor_sync(0xffffffffu, cm[ni][cl], o);
                    }
                }
            if (g == 0) {
                #pragma unroll
                for (int ni = 0; ni < 8; ni++)
                    #pragma unroll
                    for (int cl = 0; cl < 2; cl++) {
                        int C = wc * 64 + ni * 8 + tq * 2 + cl;
                        colA[wr * 128 + C] = cs[ni][cl];
                        colM[wr * 128 + C] = cm[ni][cl];
                    }
            }
        }
        __syncthreads();                                   // S2

        if (tid < 128) {
            float a = rowA[tid] + rowA[128 + tid];
            float m = rowM[tid] + rowM[128 + tid];
            if (ct == 64) a -= (float)(MPAD - MCOLS) * exp2fast(C0F);
            g_allp[ct * B_ROWS + i0 + tid]   = a;
            g_matchp[ct * B_ROWS + i0 + tid] = m;
            if (needCol) {
                float ca  = colA[tid] + colA[128 + tid] + colA[256 + tid] + colA[384 + tid];
                float cmv = colM[tid] + colM[128 + tid] + colM[256 + tid] + colM[384 + tid];
                g_allp[rt * B_ROWS + j0 + tid]   = ca;
                g_matchp[rt * B_ROWS + j0 + tid] = cmv;
            }
        }

        if (k + 1 < cnt && nrt != rt) {
            load_tile(sb + OFF_A, nrt * 128, tid);
            asm volatile("cp.async.commit_group;" ::: "memory");
        }
        rt = nrt; ct = nct; buf ^= 1;
    }
}

// per-row loss: 256 blocks x 256 threads, 8-way slot split per row
__global__ void k_rows() {
    int tid = threadIdx.x;
    int q = tid >> 5, r = tid & 31;
    int i = blockIdx.x * 32 + r;     // 256 blocks
    int c0 = q * 8;
    int cn = (q == 7) ? 9 : 8;
    float all = 0.0f, match = 0.0f;
    #pragma unroll
    for (int k = 0; k < 9; k++) {
        if (k < cn) {
            int ctk = c0 + k;
            all   += g_allp[ctk * B_ROWS + i];
            match += g_matchp[ctk * B_ROWS + i];
        }
    }
    __shared__ float sa[8][32], smm[8][32];
    sa[q][r] = all; smm[q][r] = match;
    __syncthreads();
    if (q == 0) {
        all = 0.0f; match = 0.0f;
        #pragma unroll
        for (int k = 0; k < 8; k++) { all += sa[k][r]; match += smm[k][r]; }
        float pos = match;
        float neg = all - match;
        int lab = g_lab[i];
        float cntv = (float)(g_ccount[lab] - 1);
        float prob = pos / (pos + neg);
        prob = prob / (cntv + 1e-8f);
        float lv = -logf(prob + 1e-8f);
        bool msk = lv > 0.3f;
        float lsum = msk ? lv : 0.0f;
        float lcnt = msk ? 1.0f : 0.0f;
        #pragma unroll
        for (int o = 16; o; o >>= 1) {
            lsum += __shfl_xor_sync(0xffffffffu, lsum, o);
            lcnt += __shfl_xor_sync(0xffffffffu, lcnt, o);
        }
        if (r == 0) {
            atomicAdd(&g_acc[0], lsum);
            atomicAdd(&g_acc[1], lcnt);
        }
    }
}

// final: emit loss, then reset accumulators for the next graph replay
__global__ void k_final(float* out) {
    out[0] = g_acc[0] / (g_acc[1] + 1e-8f);
    g_acc[0] = 0.0f;
    g_acc[1] = 0.0f;
    #pragma unroll
    for (int c = 0; c < NCLS; c++) g_ccount[c] = 0;
}

extern "C" void kernel_launch(void* const* d_in, const int* in_sizes, int n_in,
                              void* d_out, int out_size) {
    const float* reps    = (const float*)d_in[0];
    const int*   labels  = (const int*)d_in[1];
    const float* centers = (const float*)d_in[2];
    const float* fc_w    = (const float*)d_in[3];
    const float* fc_b    = (const float*)d_in[4];
    float* out = (float*)d_out;

    cudaFuncSetAttribute(k_main, cudaFuncAttributeMaxDynamicSharedMemorySize, SMEM_BYTES);

    k_prep<<<MPAD, 128>>>(reps, labels, centers, fc_w, fc_b);
    k_main<<<NBLK, 256, SMEM_BYTES>>>();
    k_rows<<<256, 256>>>();
    k_final<<<1, 1>>>(out);
}